// round 2
// baseline (speedup 1.0000x reference)
#include <cuda_runtime.h>
#include <cstdint>
#include <cstddef>

#define B_   4
#define S_   4096
#define D_   2048
#define E_   64
#define N_   (B_*S_)          // 16384 tokens
#define TM   64               // tokens per block
#define DK   32               // D-chunk (k per stage)
#define NCH  (D_/DK)          // 64 chunks
#define NBLK (N_/TM)          // 256 blocks
#define XROW 66               // sx row stride (floats), 8B-aligned rows, 2-way-max STS conflict
#define WROW 130              // swdup row stride (floats), 8B-aligned

// Deterministic aux-loss partials (no atomics => bitwise-stable across runs)
__device__ float g_load_part[NBLK][E_];
__device__ float g_z_part[NBLK];

__device__ __forceinline__ unsigned long long pack2(float lo, float hi) {
    unsigned long long r;
    asm("mov.b64 %0, {%1, %2};" : "=l"(r) : "r"(__float_as_uint(lo)), "r"(__float_as_uint(hi)));
    return r;
}
__device__ __forceinline__ void unpack2(unsigned long long v, float &lo, float &hi) {
    unsigned int a, b;
    asm("mov.b64 {%0, %1}, %2;" : "=r"(a), "=r"(b) : "l"(v));
    lo = __uint_as_float(a); hi = __uint_as_float(b);
}
__device__ __forceinline__ void ffma2(unsigned long long &d, unsigned long long a, unsigned long long b) {
    asm("fma.rn.f32x2 %0, %1, %2, %3;" : "=l"(d) : "l"(a), "l"(b), "l"(d));
}

__global__ void __launch_bounds__(128) router_main(
    const float* __restrict__ x, const float* __restrict__ W,
    const float* __restrict__ gamma, const float* __restrict__ beta,
    const float* __restrict__ temp,
    float* __restrict__ out_rw, float* __restrict__ out_disp)
{
    // compute phase: sx [DK][XROW] (x transposed, [k][token]) + swdup [DK][WROW] ((w,w) pairs)
    // epilogue phase: epi [64][68] aliases the same storage
    __shared__ float smem_all[DK*XROW + DK*WROW];   // 6272 floats = 25 KB
    __shared__ float s_exl[4][E_];
    __shared__ float s_z[4];
    float* sx = smem_all;
    float* sw = smem_all + DK*XROW;

    const int tid = threadIdx.x;
    const int blk = blockIdx.x;
    const int gt0 = blk * TM;

    // compute-thread mapping: 8 tokens x 4 experts per thread
    const int tx = tid & 15;         // expert lane: experts e = tx + 16*i
    const int ty = tid >> 4;         // token group: tokens t0..t0+7
    const int t0 = ty * 8;

    // fill mapping: kq = k-quad (8 quads = 32 k), tl = row selector
    const int kq = tid & 7;
    const int tl = tid >> 3;         // 0..15

    unsigned long long acc[4][4];    // [token-pair p][expert i]
    #pragma unroll
    for (int p = 0; p < 4; p++)
        #pragma unroll
        for (int i = 0; i < 4; i++) acc[p][i] = 0ull;

    // prefetch chunk 0
    float4 px[4], pw[4];
    #pragma unroll
    for (int o = 0; o < 4; o++) {
        const int row = tl + 16*o;   // token (for x) / expert (for W)
        px[o] = *(const float4*)&x[(size_t)(gt0 + row) * D_ + 4*kq];
        pw[o] = *(const float4*)&W[(size_t)row * D_ + 4*kq];
    }

    for (int c = 0; c < NCH; c++) {
        // stage registers -> smem (transpose x, duplicate W)
        #pragma unroll
        for (int o = 0; o < 4; o++) {
            const int row = tl + 16*o;
            sx[(4*kq+0)*XROW + row] = px[o].x;
            sx[(4*kq+1)*XROW + row] = px[o].y;
            sx[(4*kq+2)*XROW + row] = px[o].z;
            sx[(4*kq+3)*XROW + row] = px[o].w;
            *(unsigned long long*)&sw[(4*kq+0)*WROW + 2*row] = pack2(pw[o].x, pw[o].x);
            *(unsigned long long*)&sw[(4*kq+1)*WROW + 2*row] = pack2(pw[o].y, pw[o].y);
            *(unsigned long long*)&sw[(4*kq+2)*WROW + 2*row] = pack2(pw[o].z, pw[o].z);
            *(unsigned long long*)&sw[(4*kq+3)*WROW + 2*row] = pack2(pw[o].w, pw[o].w);
        }
        __syncthreads();

        // prefetch next chunk (in flight during compute)
        if (c + 1 < NCH) {
            const int kb = (c+1) * DK;
            #pragma unroll
            for (int o = 0; o < 4; o++) {
                const int row = tl + 16*o;
                px[o] = *(const float4*)&x[(size_t)(gt0 + row) * D_ + kb + 4*kq];
                pw[o] = *(const float4*)&W[(size_t)row * D_ + kb + 4*kq];
            }
        }

        // compute: per k -> 4 LDS.64(x-pairs) + 4 LDS.64(w-dups) + 16 FFMA2
        #pragma unroll 8
        for (int k = 0; k < DK; k++) {
            unsigned long long xp[4], wp[4];
            #pragma unroll
            for (int p = 0; p < 4; p++)
                xp[p] = *(const unsigned long long*)&sx[k*XROW + t0 + 2*p];
            #pragma unroll
            for (int i = 0; i < 4; i++)
                wp[i] = *(const unsigned long long*)&sw[k*WROW + 2*(tx + 16*i)];
            #pragma unroll
            for (int p = 0; p < 4; p++)
                #pragma unroll
                for (int i = 0; i < 4; i++)
                    ffma2(acc[p][i], xp[p], wp[i]);
        }
        __syncthreads();
    }

    // ---- epilogue: dump logits tile [64 tokens][68 pad] ----
    float* epi = smem_all;
    #pragma unroll
    for (int p = 0; p < 4; p++)
        #pragma unroll
        for (int i = 0; i < 4; i++) {
            float lo, hi; unpack2(acc[p][i], lo, hi);
            epi[(t0 + 2*p    )*68 + tx + 16*i] = lo;
            epi[(t0 + 2*p + 1)*68 + tx + 16*i] = hi;
        }
    __syncthreads();

    const int warp = tid >> 5, lane = tid & 31;
    const float g0 = gamma[lane], g1 = gamma[lane + 32];
    const float bb0 = beta[lane], bb1 = beta[lane + 32];
    const float invt = 1.0f / (temp[0] + 1e-6f);

    for (int e = lane; e < E_; e += 32) s_exl[warp][e] = 0.0f;

    float zacc = 0.0f;
    for (int t = warp*16; t < warp*16 + 16; t++) {
        const float v0 = epi[t*68 + lane];
        const float v1 = epi[t*68 + lane + 32];
        // LayerNorm over experts (two-pass, biased var)
        float s = v0 + v1;
        #pragma unroll
        for (int o = 16; o; o >>= 1) s += __shfl_xor_sync(~0u, s, o);
        const float mu = s * (1.0f/64.0f);
        const float d0 = v0 - mu, d1 = v1 - mu;
        float q = d0*d0 + d1*d1;
        #pragma unroll
        for (int o = 16; o; o >>= 1) q += __shfl_xor_sync(~0u, q, o);
        const float inv = rsqrtf(q * (1.0f/64.0f) + 1e-5f);
        const float y0 = d0*inv*g0 + bb0;
        const float y1 = d1*inv*g1 + bb1;
        zacc += y0*y0 + y1*y1;
        // temperature softmax (max-subtracted)
        const float sc0 = y0*invt, sc1 = y1*invt;
        float m = fmaxf(sc0, sc1);
        #pragma unroll
        for (int o = 16; o; o >>= 1) m = fmaxf(m, __shfl_xor_sync(~0u, m, o));
        const float ex0 = __expf(sc0 - m), ex1 = __expf(sc1 - m);
        float es = ex0 + ex1;
        #pragma unroll
        for (int o = 16; o; o >>= 1) es += __shfl_xor_sync(~0u, es, o);
        const float rinv = 1.0f / es;
        const float p0 = ex0 * rinv, p1 = ex1 * rinv;
        // top-1 (tie -> lower index, matches top_k)
        float bv; int bi;
        if (p0 >= p1) { bv = p0; bi = lane; } else { bv = p1; bi = lane + 32; }
        #pragma unroll
        for (int o = 16; o; o >>= 1) {
            float ov = __shfl_xor_sync(~0u, bv, o);
            int   oi = __shfl_xor_sync(~0u, bi, o);
            if (ov > bv || (ov == bv && oi < bi)) { bv = ov; bi = oi; }
        }
        const float w1 = bv; const int i1 = bi;
        // top-2
        const float c0 = (lane      == i1) ? -1.0f : p0;
        const float c1 = (lane + 32 == i1) ? -1.0f : p1;
        if (c0 >= c1) { bv = c0; bi = lane; } else { bv = c1; bi = lane + 32; }
        #pragma unroll
        for (int o = 16; o; o >>= 1) {
            float ov = __shfl_xor_sync(~0u, bv, o);
            int   oi = __shfl_xor_sync(~0u, bi, o);
            if (ov > bv || (ov == bv && oi < bi)) { bv = ov; bi = oi; }
        }
        const float w2 = bv; const int i2 = bi;

        const size_t base = (size_t)(gt0 + t) * E_;
        out_rw[base + lane]      = p0;
        out_rw[base + lane + 32] = p1;
        out_disp[base + lane]      = (lane == i1 || lane == i2)           ? p0 : 0.0f;
        out_disp[base + lane + 32] = (lane + 32 == i1 || lane + 32 == i2) ? p1 : 0.0f;

        if (i1 == lane)           s_exl[warp][lane]      += w1;
        else if (i1 == lane + 32) s_exl[warp][lane + 32] += w1;
        if (i2 == lane)           s_exl[warp][lane]      += w2;
        else if (i2 == lane + 32) s_exl[warp][lane + 32] += w2;
    }
    #pragma unroll
    for (int o = 16; o; o >>= 1) zacc += __shfl_xor_sync(~0u, zacc, o);
    if (lane == 0) s_z[warp] = zacc;
    __syncthreads();
    if (tid < E_)
        g_load_part[blk][tid] = s_exl[0][tid] + s_exl[1][tid] + s_exl[2][tid] + s_exl[3][tid];
    if (tid == 0)
        g_z_part[blk] = s_z[0] + s_z[1] + s_z[2] + s_z[3];
}

// 1 block, 256 threads: deterministic fixed-order reductions for total_loss
__global__ void router_finalize(float* __restrict__ out_loss)
{
    __shared__ float sh[256];
    const int tid = threadIdx.x;

    const float z = g_z_part[tid];
    const int b = tid >> 6, e = tid & 63;
    float l = 0.0f;
    #pragma unroll 8
    for (int k = 0; k < S_/TM; k++) l += g_load_part[b*(S_/TM) + k][e];
    l *= (1.0f / S_);                       // expert_load[b][e]

    sh[tid] = l; __syncthreads();
    for (int o = 128; o; o >>= 1) { if (tid < o) sh[tid] += sh[tid + o]; __syncthreads(); }
    const float mean = sh[0] * (1.0f/256.0f);
    __syncthreads();

    const float d = l - mean;
    sh[tid] = d * d; __syncthreads();
    for (int o = 128; o; o >>= 1) { if (tid < o) sh[tid] += sh[tid + o]; __syncthreads(); }
    const float var = sh[0] * (1.0f/255.0f);   // ddof=1
    __syncthreads();

    sh[tid] = z; __syncthreads();
    for (int o = 128; o; o >>= 1) { if (tid < o) sh[tid] += sh[tid + o]; __syncthreads(); }

    if (tid == 0) {
        const float zmean = sh[0] / (float)((size_t)N_ * E_);
        const float lb = (sqrtf(var) / mean) * 10.0f;
        out_loss[0] = 0.001f * zmean + 0.1f * lb;
    }
}

extern "C" void kernel_launch(void* const* d_in, const int* in_sizes, int n_in,
                              void* d_out, int out_size)
{
    (void)in_sizes; (void)n_in; (void)out_size;
    const float* x     = (const float*)d_in[0];
    const float* W     = (const float*)d_in[1];
    const float* gamma = (const float*)d_in[2];
    const float* beta  = (const float*)d_in[3];
    const float* temp  = (const float*)d_in[4];

    float* out  = (float*)d_out;
    float* rw   = out;                          // routing_weights [N,E]
    float* disp = out + (size_t)N_ * E_;        // dispatch        [B,S,E]
    float* loss = out + (size_t)2 * N_ * E_;    // total_loss scalar

    router_main<<<NBLK, 128>>>(x, W, gamma, beta, temp, rw, disp);
    router_finalize<<<1, 256>>>(loss);
}

// round 3
// speedup vs baseline: 1.1593x; 1.1593x over previous
#include <cuda_runtime.h>
#include <cstdint>
#include <cstddef>

#define B_   4
#define S_   4096
#define D_   2048
#define E_   64
#define N_   (B_*S_)          // 16384 tokens
#define TM   64               // tokens per block
#define DK   32               // D-chunk (k per stage)
#define HK   16               // k per half-group per chunk
#define NCH  (D_/DK)          // 64 chunks
#define NBLK (N_/TM)          // 256 blocks
#define XROW 66               // sx row stride (floats)
#define WROW 130              // sw dup row stride (floats)

// Deterministic aux-loss partials (no atomics on data => bitwise-stable)
__device__ float g_load_part[NBLK][E_];
__device__ float g_z_part[NBLK];
__device__ unsigned int g_cnt = 0;

__device__ __forceinline__ unsigned long long pack2(float lo, float hi) {
    unsigned long long r;
    asm("mov.b64 %0, {%1, %2};" : "=l"(r) : "r"(__float_as_uint(lo)), "r"(__float_as_uint(hi)));
    return r;
}
__device__ __forceinline__ void unpack2(unsigned long long v, float &lo, float &hi) {
    unsigned int a, b;
    asm("mov.b64 {%0, %1}, %2;" : "=r"(a), "=r"(b) : "l"(v));
    lo = __uint_as_float(a); hi = __uint_as_float(b);
}
__device__ __forceinline__ void ffma2(unsigned long long &d, unsigned long long a, unsigned long long b) {
    asm("fma.rn.f32x2 %0, %1, %2, %3;" : "=l"(d) : "l"(a), "l"(b), "l"(d));
}

__global__ void __launch_bounds__(128) router_main(
    const float* __restrict__ x, const float* __restrict__ W,
    const float* __restrict__ gamma, const float* __restrict__ beta,
    const float* __restrict__ temp,
    float* __restrict__ out_rw, float* __restrict__ out_disp,
    float* __restrict__ out_loss)
{
    // compute phase: sx [DK][XROW] + swdup [DK][WROW] = 6272 floats
    // epilogue phase: epi [2][64][68] = 8704 floats (union)
    __shared__ float smem_all[2*64*68];
    __shared__ float s_exl[4][E_];
    __shared__ float s_z[4];
    __shared__ unsigned int s_last;
    float* sx = smem_all;
    float* sw = smem_all + DK*XROW;

    const int tid = threadIdx.x;
    const int blk = blockIdx.x;
    const int gt0 = blk * TM;

    // compute mapping: two half-K groups of 64 threads; 8 tok x 8 exp per thread
    const int kh = tid >> 6;         // k-half (0/1)
    const int th = tid & 63;
    const int tx = th & 7;           // expert lane: e = tx + 8*i
    const int ty = th >> 3;          // token group
    const int t0 = ty * 8;

    // fill mapping (all 128 threads): kq = k-quad, tl = row selector
    const int kq = tid & 7;
    const int tl = tid >> 3;         // 0..15

    unsigned long long acc[4][8];    // [token-pair p][expert i]
    #pragma unroll
    for (int p = 0; p < 4; p++)
        #pragma unroll
        for (int i = 0; i < 8; i++) acc[p][i] = 0ull;

    // prefetch chunk 0
    float4 px[4], pw[4];
    #pragma unroll
    for (int o = 0; o < 4; o++) {
        const int row = tl + 16*o;
        px[o] = *(const float4*)&x[(size_t)(gt0 + row) * D_ + 4*kq];
        pw[o] = *(const float4*)&W[(size_t)row * D_ + 4*kq];
    }

    for (int c = 0; c < NCH; c++) {
        // stage registers -> smem (transpose x, duplicate W)
        #pragma unroll
        for (int o = 0; o < 4; o++) {
            const int row = tl + 16*o;
            sx[(4*kq+0)*XROW + row] = px[o].x;
            sx[(4*kq+1)*XROW + row] = px[o].y;
            sx[(4*kq+2)*XROW + row] = px[o].z;
            sx[(4*kq+3)*XROW + row] = px[o].w;
            *(unsigned long long*)&sw[(4*kq+0)*WROW + 2*row] = pack2(pw[o].x, pw[o].x);
            *(unsigned long long*)&sw[(4*kq+1)*WROW + 2*row] = pack2(pw[o].y, pw[o].y);
            *(unsigned long long*)&sw[(4*kq+2)*WROW + 2*row] = pack2(pw[o].z, pw[o].z);
            *(unsigned long long*)&sw[(4*kq+3)*WROW + 2*row] = pack2(pw[o].w, pw[o].w);
        }
        __syncthreads();

        // prefetch next chunk
        if (c + 1 < NCH) {
            const int kb = (c+1) * DK;
            #pragma unroll
            for (int o = 0; o < 4; o++) {
                const int row = tl + 16*o;
                px[o] = *(const float4*)&x[(size_t)(gt0 + row) * D_ + kb + 4*kq];
                pw[o] = *(const float4*)&W[(size_t)row * D_ + kb + 4*kq];
            }
        }

        // compute this half-group's 16 k: 4 xp + 8 wp LDS.64 -> 32 FFMA2 per k
        const float* sxk = sx + kh*HK*XROW;
        const float* swk = sw + kh*HK*WROW;
        #pragma unroll
        for (int kk = 0; kk < HK; kk++) {
            unsigned long long xp[4], wp[8];
            #pragma unroll
            for (int p = 0; p < 4; p++)
                xp[p] = *(const unsigned long long*)&sxk[kk*XROW + t0 + 2*p];
            #pragma unroll
            for (int i = 0; i < 8; i++)
                wp[i] = *(const unsigned long long*)&swk[kk*WROW + 2*(tx + 8*i)];
            #pragma unroll
            for (int p = 0; p < 4; p++)
                #pragma unroll
                for (int i = 0; i < 8; i++)
                    ffma2(acc[p][i], xp[p], wp[i]);
        }
        __syncthreads();
    }

    // ---- dump partial logits: epi[kh][64 tokens][68 pad] ----
    float* epi = smem_all;
    {
        float* ep = epi + kh*64*68;
        #pragma unroll
        for (int p = 0; p < 4; p++)
            #pragma unroll
            for (int i = 0; i < 8; i++) {
                float lo, hi; unpack2(acc[p][i], lo, hi);
                ep[(t0 + 2*p    )*68 + tx + 8*i] = lo;
                ep[(t0 + 2*p + 1)*68 + tx + 8*i] = hi;
            }
    }
    __syncthreads();

    const int warp = tid >> 5, lane = tid & 31;
    const float g0 = gamma[lane], g1 = gamma[lane + 32];
    const float bb0 = beta[lane], bb1 = beta[lane + 32];
    const float invt = 1.0f / (temp[0] + 1e-6f);

    for (int e = lane; e < E_; e += 32) s_exl[warp][e] = 0.0f;

    float zacc = 0.0f;
    for (int t = warp*16; t < warp*16 + 16; t++) {
        const float v0 = epi[t*68 + lane]      + epi[64*68 + t*68 + lane];
        const float v1 = epi[t*68 + lane + 32] + epi[64*68 + t*68 + lane + 32];
        // LayerNorm over experts (two-pass, biased var)
        float s = v0 + v1;
        #pragma unroll
        for (int o = 16; o; o >>= 1) s += __shfl_xor_sync(~0u, s, o);
        const float mu = s * (1.0f/64.0f);
        const float d0 = v0 - mu, d1 = v1 - mu;
        float q = d0*d0 + d1*d1;
        #pragma unroll
        for (int o = 16; o; o >>= 1) q += __shfl_xor_sync(~0u, q, o);
        const float inv = rsqrtf(q * (1.0f/64.0f) + 1e-5f);
        const float y0 = d0*inv*g0 + bb0;
        const float y1 = d1*inv*g1 + bb1;
        zacc += y0*y0 + y1*y1;
        // temperature softmax
        const float sc0 = y0*invt, sc1 = y1*invt;
        float m = fmaxf(sc0, sc1);
        #pragma unroll
        for (int o = 16; o; o >>= 1) m = fmaxf(m, __shfl_xor_sync(~0u, m, o));
        const float ex0 = __expf(sc0 - m), ex1 = __expf(sc1 - m);
        float es = ex0 + ex1;
        #pragma unroll
        for (int o = 16; o; o >>= 1) es += __shfl_xor_sync(~0u, es, o);
        const float rinv = 1.0f / es;
        const float p0 = ex0 * rinv, p1 = ex1 * rinv;
        // top-1 (tie -> lower index)
        float bv; int bi;
        if (p0 >= p1) { bv = p0; bi = lane; } else { bv = p1; bi = lane + 32; }
        #pragma unroll
        for (int o = 16; o; o >>= 1) {
            float ov = __shfl_xor_sync(~0u, bv, o);
            int   oi = __shfl_xor_sync(~0u, bi, o);
            if (ov > bv || (ov == bv && oi < bi)) { bv = ov; bi = oi; }
        }
        const float w1 = bv; const int i1 = bi;
        // top-2
        const float c0 = (lane      == i1) ? -1.0f : p0;
        const float c1 = (lane + 32 == i1) ? -1.0f : p1;
        if (c0 >= c1) { bv = c0; bi = lane; } else { bv = c1; bi = lane + 32; }
        #pragma unroll
        for (int o = 16; o; o >>= 1) {
            float ov = __shfl_xor_sync(~0u, bv, o);
            int   oi = __shfl_xor_sync(~0u, bi, o);
            if (ov > bv || (ov == bv && oi < bi)) { bv = ov; bi = oi; }
        }
        const float w2 = bv; const int i2 = bi;

        const size_t base = (size_t)(gt0 + t) * E_;
        out_rw[base + lane]      = p0;
        out_rw[base + lane + 32] = p1;
        out_disp[base + lane]      = (lane == i1 || lane == i2)           ? p0 : 0.0f;
        out_disp[base + lane + 32] = (lane + 32 == i1 || lane + 32 == i2) ? p1 : 0.0f;

        if (i1 == lane)           s_exl[warp][lane]      += w1;
        else if (i1 == lane + 32) s_exl[warp][lane + 32] += w1;
        if (i2 == lane)           s_exl[warp][lane]      += w2;
        else if (i2 == lane + 32) s_exl[warp][lane + 32] += w2;
    }
    #pragma unroll
    for (int o = 16; o; o >>= 1) zacc += __shfl_xor_sync(~0u, zacc, o);
    if (lane == 0) s_z[warp] = zacc;
    __syncthreads();
    if (tid < E_)
        g_load_part[blk][tid] = s_exl[0][tid] + s_exl[1][tid] + s_exl[2][tid] + s_exl[3][tid];
    if (tid == 0)
        g_z_part[blk] = s_z[0] + s_z[1] + s_z[2] + s_z[3];

    // ---- last-block finalize (deterministic fixed-order reductions) ----
    __threadfence();
    if (tid == 0) s_last = (atomicAdd(&g_cnt, 1) == NBLK - 1) ? 1u : 0u;
    __syncthreads();
    if (!s_last) return;
    if (tid == 0) g_cnt = 0;               // reset for next graph replay
    __threadfence();

    float* sh = smem_all;                  // 256-float scratch
    float lcell[2], zcell[2];
    #pragma unroll
    for (int h = 0; h < 2; h++) {
        const int cidx = tid + h*128;
        const int b = cidx >> 6, e = cidx & 63;
        float a = 0.0f;
        #pragma unroll 8
        for (int k = 0; k < S_/TM; k++) a += g_load_part[b*(S_/TM) + k][e];
        lcell[h] = a * (1.0f / S_);
        zcell[h] = g_z_part[cidx];
    }
    sh[tid] = lcell[0]; sh[tid+128] = lcell[1];
    __syncthreads();
    for (int o = 128; o; o >>= 1) { if (tid < o) sh[tid] += sh[tid + o]; __syncthreads(); }
    const float mean = sh[0] * (1.0f/256.0f);
    __syncthreads();

    const float dd0 = lcell[0] - mean, dd1 = lcell[1] - mean;
    sh[tid] = dd0*dd0; sh[tid+128] = dd1*dd1;
    __syncthreads();
    for (int o = 128; o; o >>= 1) { if (tid < o) sh[tid] += sh[tid + o]; __syncthreads(); }
    const float var = sh[0] * (1.0f/255.0f);   // ddof=1
    __syncthreads();

    sh[tid] = zcell[0]; sh[tid+128] = zcell[1];
    __syncthreads();
    for (int o = 128; o; o >>= 1) { if (tid < o) sh[tid] += sh[tid + o]; __syncthreads(); }

    if (tid == 0) {
        const float zmean = sh[0] / (float)((size_t)N_ * E_);
        const float lb = (sqrtf(var) / mean) * 10.0f;
        out_loss[0] = 0.001f * zmean + 0.1f * lb;
    }
}

extern "C" void kernel_launch(void* const* d_in, const int* in_sizes, int n_in,
                              void* d_out, int out_size)
{
    (void)in_sizes; (void)n_in; (void)out_size;
    const float* x     = (const float*)d_in[0];
    const float* W     = (const float*)d_in[1];
    const float* gamma = (const float*)d_in[2];
    const float* beta  = (const float*)d_in[3];
    const float* temp  = (const float*)d_in[4];

    float* out  = (float*)d_out;
    float* rw   = out;                          // routing_weights [N,E]
    float* disp = out + (size_t)N_ * E_;        // dispatch        [B,S,E]
    float* loss = out + (size_t)2 * N_ * E_;    // total_loss scalar

    router_main<<<NBLK, 128>>>(x, W, gamma, beta, temp, rw, disp, loss);
}

// round 6
// speedup vs baseline: 2.0211x; 1.7433x over previous
#include <cuda_runtime.h>
#include <cuda_bf16.h>
#include <cstdint>
#include <cstddef>

#define B_   4
#define S_   4096
#define D_   2048
#define E_   64
#define N_   (B_*S_)          // 16384
#define TM   128              // tokens per block
#define NBLK (N_/TM)          // 128 blocks
#define KC   32               // k per chunk
#define NCH  (D_/KC)          // 64 chunks
#define NBPB (S_/TM)          // 32 blocks per batch

// smem tile geometry: bf16, row stride 40 elems = 80B (bank-conflict-free ldmatrix)
#define AST  40
#define ATILE (TM*AST*2)      // 10240 B
#define BTILE (E_*AST*2)      // 5120 B
#define OFF_AHI 0
#define OFF_ALO ATILE
#define OFF_BHI (2*ATILE)
#define OFF_BLO (2*ATILE + BTILE)
#define EPI_BYTES (TM*68*4)   // 34816 B > 30720 B of tiles (union)

__device__ float g_load_part[NBLK][E_];
__device__ float g_z_part[NBLK];
__device__ unsigned int g_cnt = 0;

__device__ __forceinline__ uint32_t smem_u32(const void* p) {
    uint32_t a;
    asm("{ .reg .u64 t; cvta.to.shared.u64 t, %1; cvt.u32.u64 %0, t; }" : "=r"(a) : "l"(p));
    return a;
}
__device__ __forceinline__ void ldsm4(uint32_t* r, uint32_t addr) {
    asm volatile("ldmatrix.sync.aligned.m8n8.x4.shared.b16 {%0,%1,%2,%3}, [%4];"
                 : "=r"(r[0]), "=r"(r[1]), "=r"(r[2]), "=r"(r[3]) : "r"(addr));
}
__device__ __forceinline__ void mma_bf16(float* d, const uint32_t* a, uint32_t b0, uint32_t b1) {
    asm volatile(
        "mma.sync.aligned.m16n8k16.row.col.f32.bf16.bf16.f32 "
        "{%0,%1,%2,%3}, {%4,%5,%6,%7}, {%8,%9}, {%0,%1,%2,%3};"
        : "+f"(d[0]), "+f"(d[1]), "+f"(d[2]), "+f"(d[3])
        : "r"(a[0]), "r"(a[1]), "r"(a[2]), "r"(a[3]), "r"(b0), "r"(b1));
}
__device__ __forceinline__ void cvt_hilo(float a, float b, uint32_t &hi, uint32_t &lo) {
    __nv_bfloat162 h = __floats2bfloat162_rn(a, b);
    hi = *reinterpret_cast<uint32_t*>(&h);
    float ra = a - __bfloat162float(h.x);
    float rb = b - __bfloat162float(h.y);
    __nv_bfloat162 l = __floats2bfloat162_rn(ra, rb);
    lo = *reinterpret_cast<uint32_t*>(&l);
}

__global__ void __launch_bounds__(256) router_main(
    const float* __restrict__ x, const float* __restrict__ W,
    const float* __restrict__ gamma, const float* __restrict__ beta,
    const float* __restrict__ temp,
    float* __restrict__ out_rw, float* __restrict__ out_disp,
    float* __restrict__ out_loss)
{
    __shared__ __align__(16) char smtiles[EPI_BYTES];   // tiles, then epi[128][68]
    __shared__ float s_exl[8][E_];
    __shared__ float s_z[8];
    __shared__ unsigned int s_last;

    const uint32_t sb = smem_u32(smtiles);
    const int tid = threadIdx.x;
    const int wid = tid >> 5, lane = tid & 31;
    const int blk = blockIdx.x;
    const int gt0 = blk * TM;

    // ---- fill mapping ----
    const int xrow = tid >> 1, xk0 = (tid & 1) * 16;    // x: 2 thr/row, 16 k each
    const int wrow = tid >> 2, wk0 = (tid & 3) * 8;     // W: 4 thr/row, 8 k each
    const float* xbase = x + (size_t)(gt0 + xrow) * D_ + xk0;
    const float* wbase = W + (size_t)wrow * D_ + wk0;

    float4 px[4], pw[2];
    #pragma unroll
    for (int i = 0; i < 4; i++) px[i] = *(const float4*)(xbase + 4*i);
    #pragma unroll
    for (int i = 0; i < 2; i++) pw[i] = *(const float4*)(wbase + 4*i);

    // ---- ldmatrix lane addresses ----
    const int g = lane >> 3, rif = lane & 7;
    const int m0 = wid * 16;
    // A: g0:(m0-7,k0) g1:(m8-15,k0) g2:(m0-7,k8) g3:(m8-15,k8)
    const uint32_t aoff = (uint32_t)(m0 + (g & 1)*8 + rif) * 80u + (uint32_t)((g >> 1)*8) * 2u;
    // B: g0:(n0-7,k0) g1:(n0-7,k8) g2:(n8-15,k0) g3:(n8-15,k8)
    const uint32_t boff = (uint32_t)((g >> 1)*8 + rif) * 80u + (uint32_t)((g & 1)*8) * 2u;

    float acc[8][4];
    #pragma unroll
    for (int t = 0; t < 8; t++)
        #pragma unroll
        for (int i = 0; i < 4; i++) acc[t][i] = 0.0f;

    for (int c = 0; c < NCH; c++) {
        // stage regs -> smem (bf16 hi/lo, conflict-light 8B stores)
        #pragma unroll
        for (int i = 0; i < 4; i++) {
            const uint32_t byt = (uint32_t)xrow * 80u + (uint32_t)(xk0 + 4*i) * 2u;
            uint32_t h01, l01, h23, l23;
            cvt_hilo(px[i].x, px[i].y, h01, l01);
            cvt_hilo(px[i].z, px[i].w, h23, l23);
            *(uint2*)(smtiles + OFF_AHI + byt) = make_uint2(h01, h23);
            *(uint2*)(smtiles + OFF_ALO + byt) = make_uint2(l01, l23);
        }
        #pragma unroll
        for (int i = 0; i < 2; i++) {
            const uint32_t byt = (uint32_t)wrow * 80u + (uint32_t)(wk0 + 4*i) * 2u;
            uint32_t h01, l01, h23, l23;
            cvt_hilo(pw[i].x, pw[i].y, h01, l01);
            cvt_hilo(pw[i].z, pw[i].w, h23, l23);
            *(uint2*)(smtiles + OFF_BHI + byt) = make_uint2(h01, h23);
            *(uint2*)(smtiles + OFF_BLO + byt) = make_uint2(l01, l23);
        }
        __syncthreads();

        if (c + 1 < NCH) {
            const int kb = (c + 1) * KC;
            #pragma unroll
            for (int i = 0; i < 4; i++) px[i] = *(const float4*)(xbase + kb + 4*i);
            #pragma unroll
            for (int i = 0; i < 2; i++) pw[i] = *(const float4*)(wbase + kb + 4*i);
        }

        // two k16 steps per chunk
        #pragma unroll
        for (int s = 0; s < 2; s++) {
            const uint32_t kb = (uint32_t)s * 32u;   // 16 bf16 = 32B
            uint32_t ah[4], al[4], bh[16], bl[16];
            ldsm4(ah, sb + OFF_AHI + aoff + kb);
            ldsm4(al, sb + OFF_ALO + aoff + kb);
            #pragma unroll
            for (int j = 0; j < 4; j++)
                ldsm4(&bh[4*j], sb + OFF_BHI + boff + (uint32_t)j * 1280u + kb);
            #pragma unroll
            for (int t = 0; t < 8; t++) {
                const int bi = 4*(t >> 1) + (t & 1)*2;
                mma_bf16(acc[t], ah, bh[bi], bh[bi+1]);   // hi*hi
                mma_bf16(acc[t], al, bh[bi], bh[bi+1]);   // lo*hi
            }
            #pragma unroll
            for (int j = 0; j < 4; j++)
                ldsm4(&bl[4*j], sb + OFF_BLO + boff + (uint32_t)j * 1280u + kb);
            #pragma unroll
            for (int t = 0; t < 8; t++) {
                const int bi = 4*(t >> 1) + (t & 1)*2;
                mma_bf16(acc[t], ah, bl[bi], bl[bi+1]);   // hi*lo
            }
        }
        __syncthreads();
    }

    // ---- acc -> epi[128][68] ----
    float* epi = (float*)smtiles;
    {
        const int r0 = m0 + (lane >> 2);
        const int cq = (lane & 3) * 2;
        #pragma unroll
        for (int t = 0; t < 8; t++) {
            *(float2*)&epi[(r0    )*68 + t*8 + cq] = make_float2(acc[t][0], acc[t][1]);
            *(float2*)&epi[(r0 + 8)*68 + t*8 + cq] = make_float2(acc[t][2], acc[t][3]);
        }
    }
    __syncthreads();

    // ---- LN / softmax / top-2 (8 warps x 16 tokens) ----
    const float g0v = gamma[lane], g1v = gamma[lane + 32];
    const float bb0 = beta[lane], bb1 = beta[lane + 32];
    const float invt = 1.0f / (temp[0] + 1e-6f);

    for (int e = lane; e < E_; e += 32) s_exl[wid][e] = 0.0f;

    float zacc = 0.0f;
    for (int t = wid*16; t < wid*16 + 16; t++) {
        const float v0 = epi[t*68 + lane];
        const float v1 = epi[t*68 + lane + 32];
        float sm = v0 + v1;
        #pragma unroll
        for (int o = 16; o; o >>= 1) sm += __shfl_xor_sync(~0u, sm, o);
        const float mu = sm * (1.0f/64.0f);
        const float d0 = v0 - mu, d1 = v1 - mu;
        float q = d0*d0 + d1*d1;
        #pragma unroll
        for (int o = 16; o; o >>= 1) q += __shfl_xor_sync(~0u, q, o);
        const float inv = rsqrtf(q * (1.0f/64.0f) + 1e-5f);
        const float y0 = d0*inv*g0v + bb0;
        const float y1 = d1*inv*g1v + bb1;
        zacc += y0*y0 + y1*y1;
        const float sc0 = y0*invt, sc1 = y1*invt;
        float m = fmaxf(sc0, sc1);
        #pragma unroll
        for (int o = 16; o; o >>= 1) m = fmaxf(m, __shfl_xor_sync(~0u, m, o));
        const float ex0 = __expf(sc0 - m), ex1 = __expf(sc1 - m);
        float es = ex0 + ex1;
        #pragma unroll
        for (int o = 16; o; o >>= 1) es += __shfl_xor_sync(~0u, es, o);
        const float rinv = 1.0f / es;
        const float p0 = ex0 * rinv, p1 = ex1 * rinv;
        float bv; int bi;
        if (p0 >= p1) { bv = p0; bi = lane; } else { bv = p1; bi = lane + 32; }
        #pragma unroll
        for (int o = 16; o; o >>= 1) {
            float ov = __shfl_xor_sync(~0u, bv, o);
            int   oi = __shfl_xor_sync(~0u, bi, o);
            if (ov > bv || (ov == bv && oi < bi)) { bv = ov; bi = oi; }
        }
        const float w1 = bv; const int i1 = bi;
        const float c0 = (lane      == i1) ? -1.0f : p0;
        const float c1 = (lane + 32 == i1) ? -1.0f : p1;
        if (c0 >= c1) { bv = c0; bi = lane; } else { bv = c1; bi = lane + 32; }
        #pragma unroll
        for (int o = 16; o; o >>= 1) {
            float ov = __shfl_xor_sync(~0u, bv, o);
            int   oi = __shfl_xor_sync(~0u, bi, o);
            if (ov > bv || (ov == bv && oi < bi)) { bv = ov; bi = oi; }
        }
        const float w2 = bv; const int i2 = bi;

        const size_t base = (size_t)(gt0 + t) * E_;
        out_rw[base + lane]      = p0;
        out_rw[base + lane + 32] = p1;
        out_disp[base + lane]      = (lane == i1 || lane == i2)           ? p0 : 0.0f;
        out_disp[base + lane + 32] = (lane + 32 == i1 || lane + 32 == i2) ? p1 : 0.0f;

        if (i1 == lane)           s_exl[wid][lane]      += w1;
        else if (i1 == lane + 32) s_exl[wid][lane + 32] += w1;
        if (i2 == lane)           s_exl[wid][lane]      += w2;
        else if (i2 == lane + 32) s_exl[wid][lane + 32] += w2;
    }
    #pragma unroll
    for (int o = 16; o; o >>= 1) zacc += __shfl_xor_sync(~0u, zacc, o);
    if (lane == 0) s_z[wid] = zacc;
    __syncthreads();

    if (tid < E_) {
        float a = 0.0f;
        #pragma unroll
        for (int w = 0; w < 8; w++) a += s_exl[w][tid];
        g_load_part[blk][tid] = a;
    }
    if (tid == 0)
        g_z_part[blk] = s_z[0]+s_z[1]+s_z[2]+s_z[3]+s_z[4]+s_z[5]+s_z[6]+s_z[7];

    // ---- last-block finalize (deterministic) ----
    __threadfence();
    if (tid == 0) s_last = (atomicAdd(&g_cnt, 1) == NBLK - 1) ? 1u : 0u;
    __syncthreads();
    if (!s_last) return;
    if (tid == 0) g_cnt = 0;
    __threadfence();

    float* red = (float*)smtiles;
    const int b = tid >> 6, e = tid & 63;
    float l = 0.0f;
    #pragma unroll 8
    for (int k = 0; k < NBPB; k++) l += g_load_part[b * NBPB + k][e];
    l *= (1.0f / S_);
    const float zc = (tid < NBLK) ? g_z_part[tid] : 0.0f;

    __syncthreads();
    red[tid] = l; __syncthreads();
    for (int o = 128; o; o >>= 1) { if (tid < o) red[tid] += red[tid + o]; __syncthreads(); }
    const float mean = red[0] * (1.0f / 256.0f);
    __syncthreads();

    const float dd = l - mean;
    red[tid] = dd * dd; __syncthreads();
    for (int o = 128; o; o >>= 1) { if (tid < o) red[tid] += red[tid + o]; __syncthreads(); }
    const float var = red[0] * (1.0f / 255.0f);
    __syncthreads();

    red[tid] = zc; __syncthreads();
    for (int o = 128; o; o >>= 1) { if (tid < o) red[tid] += red[tid + o]; __syncthreads(); }

    if (tid == 0) {
        const float zmean = red[0] / (float)((size_t)N_ * E_);
        const float lb = (sqrtf(var) / mean) * 10.0f;
        out_loss[0] = 0.001f * zmean + 0.1f * lb;
    }
}

extern "C" void kernel_launch(void* const* d_in, const int* in_sizes, int n_in,
                              void* d_out, int out_size)
{
    (void)in_sizes; (void)n_in; (void)out_size;
    const float* x     = (const float*)d_in[0];
    const float* W     = (const float*)d_in[1];
    const float* gamma = (const float*)d_in[2];
    const float* beta  = (const float*)d_in[3];
    const float* temp  = (const float*)d_in[4];

    float* out  = (float*)d_out;
    float* rw   = out;
    float* disp = out + (size_t)N_ * E_;
    float* loss = out + (size_t)2 * N_ * E_;

    router_main<<<NBLK, 256>>>(x, W, gamma, beta, temp, rw, disp, loss);
}

// round 7
// speedup vs baseline: 2.5059x; 1.2399x over previous
#include <cuda_runtime.h>
#include <cuda_bf16.h>
#include <cstdint>
#include <cstddef>

#define B_   4
#define S_   4096
#define D_   2048
#define E_   64
#define N_   (B_*S_)          // 16384
#define TM   64               // tokens per block
#define NBLK (N_/TM)          // 256 blocks
#define KC   32               // k per chunk
#define NCH  (D_/KC)          // 64 chunks
#define NBPB (S_/TM)          // 64 blocks per batch

// smem tiles: bf16, row stride 40 elems = 80B (conflict-free ldmatrix)
#define OFF_AHI 0
#define OFF_ALO (TM*80)           // 5120
#define OFF_BHI (2*TM*80)         // 10240
#define OFF_BLO (2*TM*80 + E_*80) // 15360
#define EPI_BYTES (2*TM*68*4)     // 34816 B (union over 20480 B of tiles)

__device__ float g_load_part[NBLK][E_];
__device__ float g_z_part[NBLK];
__device__ unsigned int g_cnt = 0;

__device__ __forceinline__ uint32_t smem_u32(const void* p) {
    uint32_t a;
    asm("{ .reg .u64 t; cvta.to.shared.u64 t, %1; cvt.u32.u64 %0, t; }" : "=r"(a) : "l"(p));
    return a;
}
__device__ __forceinline__ void ldsm4(uint32_t* r, uint32_t addr) {
    asm volatile("ldmatrix.sync.aligned.m8n8.x4.shared.b16 {%0,%1,%2,%3}, [%4];"
                 : "=r"(r[0]), "=r"(r[1]), "=r"(r[2]), "=r"(r[3]) : "r"(addr));
}
__device__ __forceinline__ void mma_bf16(float* d, const uint32_t* a, uint32_t b0, uint32_t b1) {
    asm volatile(
        "mma.sync.aligned.m16n8k16.row.col.f32.bf16.bf16.f32 "
        "{%0,%1,%2,%3}, {%4,%5,%6,%7}, {%8,%9}, {%0,%1,%2,%3};"
        : "+f"(d[0]), "+f"(d[1]), "+f"(d[2]), "+f"(d[3])
        : "r"(a[0]), "r"(a[1]), "r"(a[2]), "r"(a[3]), "r"(b0), "r"(b1));
}
__device__ __forceinline__ void cvt_hilo(float a, float b, uint32_t &hi, uint32_t &lo) {
    __nv_bfloat162 h = __floats2bfloat162_rn(a, b);
    hi = *reinterpret_cast<uint32_t*>(&h);
    float ra = a - __bfloat162float(h.x);
    float rb = b - __bfloat162float(h.y);
    __nv_bfloat162 l = __floats2bfloat162_rn(ra, rb);
    lo = *reinterpret_cast<uint32_t*>(&l);
}

__global__ void __launch_bounds__(256) router_main(
    const float* __restrict__ x, const float* __restrict__ W,
    const float* __restrict__ gamma, const float* __restrict__ beta,
    const float* __restrict__ temp,
    float* __restrict__ out_rw, float* __restrict__ out_disp,
    float* __restrict__ out_loss)
{
    __shared__ __align__(16) char smtiles[EPI_BYTES];   // tiles, then epi[2][64][68]
    __shared__ float s_exl[8][E_];
    __shared__ float s_z[8];
    __shared__ unsigned int s_last;

    const uint32_t sb = smem_u32(smtiles);
    const int tid = threadIdx.x;
    const int wid = tid >> 5, lane = tid & 31;
    const int blk = blockIdx.x;
    const int gt0 = blk * TM;

    // ---- fill mapping: 4 thr/row, 8 floats each (both tiles are 64 x 32) ----
    const int frow = tid >> 2, fk0 = (tid & 3) * 8;
    const float* xbase = x + (size_t)(gt0 + frow) * D_ + fk0;
    const float* wbase = W + (size_t)frow * D_ + fk0;

    float4 px[2], pw[2];
    #pragma unroll
    for (int i = 0; i < 2; i++) px[i] = *(const float4*)(xbase + 4*i);
    #pragma unroll
    for (int i = 0; i < 2; i++) pw[i] = *(const float4*)(wbase + 4*i);

    // ---- warp tile: m32 x n32 x k-half ----
    const int mg = wid & 1, ng = (wid >> 1) & 1, kg = wid >> 2;
    const int g = lane >> 3, rif = lane & 7;
    const uint32_t kgb = (uint32_t)kg * 32u;    // k16 offset in bytes
    uint32_t aoff[2], boff[2];
    #pragma unroll
    for (int s = 0; s < 2; s++)
        aoff[s] = (uint32_t)(mg*32 + s*16 + (g & 1)*8 + rif) * 80u + (uint32_t)((g >> 1)*8) * 2u + kgb;
    #pragma unroll
    for (int j = 0; j < 2; j++)
        boff[j] = (uint32_t)(ng*32 + j*16 + (g >> 1)*8 + rif) * 80u + (uint32_t)((g & 1)*8) * 2u + kgb;

    float acc[2][4][4];
    #pragma unroll
    for (int s = 0; s < 2; s++)
        #pragma unroll
        for (int j = 0; j < 4; j++)
            #pragma unroll
            for (int i = 0; i < 4; i++) acc[s][j][i] = 0.0f;

    for (int c = 0; c < NCH; c++) {
        // stage regs -> smem (bf16 hi/lo)
        #pragma unroll
        for (int i = 0; i < 2; i++) {
            const uint32_t byt = (uint32_t)frow * 80u + (uint32_t)(fk0 + 4*i) * 2u;
            uint32_t h01, l01, h23, l23;
            cvt_hilo(px[i].x, px[i].y, h01, l01);
            cvt_hilo(px[i].z, px[i].w, h23, l23);
            *(uint2*)(smtiles + OFF_AHI + byt) = make_uint2(h01, h23);
            *(uint2*)(smtiles + OFF_ALO + byt) = make_uint2(l01, l23);
            uint32_t wh01, wl01, wh23, wl23;
            cvt_hilo(pw[i].x, pw[i].y, wh01, wl01);
            cvt_hilo(pw[i].z, pw[i].w, wh23, wl23);
            *(uint2*)(smtiles + OFF_BHI + byt) = make_uint2(wh01, wh23);
            *(uint2*)(smtiles + OFF_BLO + byt) = make_uint2(wl01, wl23);
        }
        __syncthreads();

        if (c + 1 < NCH) {
            const int kb = (c + 1) * KC;
            #pragma unroll
            for (int i = 0; i < 2; i++) px[i] = *(const float4*)(xbase + kb + 4*i);
            #pragma unroll
            for (int i = 0; i < 2; i++) pw[i] = *(const float4*)(wbase + kb + 4*i);
        }

        // one k16 step per warp (its k-half)
        uint32_t ah[2][4], al[2][4], bh[8], bl[8];
        ldsm4(ah[0], sb + OFF_AHI + aoff[0]);
        ldsm4(ah[1], sb + OFF_AHI + aoff[1]);
        ldsm4(al[0], sb + OFF_ALO + aoff[0]);
        ldsm4(al[1], sb + OFF_ALO + aoff[1]);
        ldsm4(&bh[0], sb + OFF_BHI + boff[0]);
        ldsm4(&bh[4], sb + OFF_BHI + boff[1]);
        #pragma unroll
        for (int s = 0; s < 2; s++)
            #pragma unroll
            for (int j = 0; j < 4; j++) {
                mma_bf16(acc[s][j], ah[s], bh[2*j], bh[2*j + 1]);   // hi*hi
                mma_bf16(acc[s][j], al[s], bh[2*j], bh[2*j + 1]);   // lo*hi
            }
        ldsm4(&bl[0], sb + OFF_BLO + boff[0]);
        ldsm4(&bl[4], sb + OFF_BLO + boff[1]);
        #pragma unroll
        for (int s = 0; s < 2; s++)
            #pragma unroll
            for (int j = 0; j < 4; j++)
                mma_bf16(acc[s][j], ah[s], bl[2*j], bl[2*j + 1]);   // hi*lo
        __syncthreads();
    }

    // ---- acc -> epi[kg][64][68] (k-half partials) ----
    float* epi = (float*)smtiles;
    {
        float* ep = epi + kg * TM * 68;
        const int rl = lane >> 2;
        const int cq = (lane & 3) * 2;
        #pragma unroll
        for (int s = 0; s < 2; s++) {
            const int r0 = mg*32 + s*16 + rl;
            #pragma unroll
            for (int j = 0; j < 4; j++) {
                const int col = ng*32 + j*8 + cq;
                *(float2*)&ep[(r0    )*68 + col] = make_float2(acc[s][j][0], acc[s][j][1]);
                *(float2*)&ep[(r0 + 8)*68 + col] = make_float2(acc[s][j][2], acc[s][j][3]);
            }
        }
    }
    __syncthreads();

    // ---- LN / softmax / top-2 (8 warps x 8 tokens) ----
    const float g0v = gamma[lane], g1v = gamma[lane + 32];
    const float bb0 = beta[lane], bb1 = beta[lane + 32];
    const float invt = 1.0f / (temp[0] + 1e-6f);

    for (int e = lane; e < E_; e += 32) s_exl[wid][e] = 0.0f;

    float zacc = 0.0f;
    for (int t = wid*8; t < wid*8 + 8; t++) {
        const float v0 = epi[t*68 + lane]      + epi[TM*68 + t*68 + lane];
        const float v1 = epi[t*68 + lane + 32] + epi[TM*68 + t*68 + lane + 32];
        float sm = v0 + v1;
        #pragma unroll
        for (int o = 16; o; o >>= 1) sm += __shfl_xor_sync(~0u, sm, o);
        const float mu = sm * (1.0f/64.0f);
        const float d0 = v0 - mu, d1 = v1 - mu;
        float q = d0*d0 + d1*d1;
        #pragma unroll
        for (int o = 16; o; o >>= 1) q += __shfl_xor_sync(~0u, q, o);
        const float inv = rsqrtf(q * (1.0f/64.0f) + 1e-5f);
        const float y0 = d0*inv*g0v + bb0;
        const float y1 = d1*inv*g1v + bb1;
        zacc += y0*y0 + y1*y1;
        const float sc0 = y0*invt, sc1 = y1*invt;
        float m = fmaxf(sc0, sc1);
        #pragma unroll
        for (int o = 16; o; o >>= 1) m = fmaxf(m, __shfl_xor_sync(~0u, m, o));
        const float ex0 = __expf(sc0 - m), ex1 = __expf(sc1 - m);
        float es = ex0 + ex1;
        #pragma unroll
        for (int o = 16; o; o >>= 1) es += __shfl_xor_sync(~0u, es, o);
        const float rinv = 1.0f / es;
        const float p0 = ex0 * rinv, p1 = ex1 * rinv;
        float bv; int bi;
        if (p0 >= p1) { bv = p0; bi = lane; } else { bv = p1; bi = lane + 32; }
        #pragma unroll
        for (int o = 16; o; o >>= 1) {
            float ov = __shfl_xor_sync(~0u, bv, o);
            int   oi = __shfl_xor_sync(~0u, bi, o);
            if (ov > bv || (ov == bv && oi < bi)) { bv = ov; bi = oi; }
        }
        const float w1 = bv; const int i1 = bi;
        const float c0 = (lane      == i1) ? -1.0f : p0;
        const float c1 = (lane + 32 == i1) ? -1.0f : p1;
        if (c0 >= c1) { bv = c0; bi = lane; } else { bv = c1; bi = lane + 32; }
        #pragma unroll
        for (int o = 16; o; o >>= 1) {
            float ov = __shfl_xor_sync(~0u, bv, o);
            int   oi = __shfl_xor_sync(~0u, bi, o);
            if (ov > bv || (ov == bv && oi < bi)) { bv = ov; bi = oi; }
        }
        const float w2 = bv; const int i2 = bi;

        const size_t base = (size_t)(gt0 + t) * E_;
        out_rw[base + lane]      = p0;
        out_rw[base + lane + 32] = p1;
        out_disp[base + lane]      = (lane == i1 || lane == i2)           ? p0 : 0.0f;
        out_disp[base + lane + 32] = (lane + 32 == i1 || lane + 32 == i2) ? p1 : 0.0f;

        if (i1 == lane)           s_exl[wid][lane]      += w1;
        else if (i1 == lane + 32) s_exl[wid][lane + 32] += w1;
        if (i2 == lane)           s_exl[wid][lane]      += w2;
        else if (i2 == lane + 32) s_exl[wid][lane + 32] += w2;
    }
    #pragma unroll
    for (int o = 16; o; o >>= 1) zacc += __shfl_xor_sync(~0u, zacc, o);
    if (lane == 0) s_z[wid] = zacc;
    __syncthreads();

    if (tid < E_) {
        float a = 0.0f;
        #pragma unroll
        for (int w = 0; w < 8; w++) a += s_exl[w][tid];
        g_load_part[blk][tid] = a;
    }
    if (tid == 0)
        g_z_part[blk] = s_z[0]+s_z[1]+s_z[2]+s_z[3]+s_z[4]+s_z[5]+s_z[6]+s_z[7];

    // ---- last-block finalize (deterministic) ----
    __threadfence();
    if (tid == 0) s_last = (atomicAdd(&g_cnt, 1) == NBLK - 1) ? 1u : 0u;
    __syncthreads();
    if (!s_last) return;
    if (tid == 0) g_cnt = 0;
    __threadfence();

    float* red = (float*)smtiles;
    const int b = tid >> 6, e = tid & 63;
    float l = 0.0f;
    #pragma unroll 8
    for (int k = 0; k < NBPB; k++) l += g_load_part[b * NBPB + k][e];
    l *= (1.0f / S_);
    const float zc = g_z_part[tid];

    __syncthreads();
    red[tid] = l; __syncthreads();
    for (int o = 128; o; o >>= 1) { if (tid < o) red[tid] += red[tid + o]; __syncthreads(); }
    const float mean = red[0] * (1.0f / 256.0f);
    __syncthreads();

    const float dd = l - mean;
    red[tid] = dd * dd; __syncthreads();
    for (int o = 128; o; o >>= 1) { if (tid < o) red[tid] += red[tid + o]; __syncthreads(); }
    const float var = red[0] * (1.0f / 255.0f);
    __syncthreads();

    red[tid] = zc; __syncthreads();
    for (int o = 128; o; o >>= 1) { if (tid < o) red[tid] += red[tid + o]; __syncthreads(); }

    if (tid == 0) {
        const float zmean = red[0] / (float)((size_t)N_ * E_);
        const float lb = (sqrtf(var) / mean) * 10.0f;
        out_loss[0] = 0.001f * zmean + 0.1f * lb;
    }
}

extern "C" void kernel_launch(void* const* d_in, const int* in_sizes, int n_in,
                              void* d_out, int out_size)
{
    (void)in_sizes; (void)n_in; (void)out_size;
    const float* x     = (const float*)d_in[0];
    const float* W     = (const float*)d_in[1];
    const float* gamma = (const float*)d_in[2];
    const float* beta  = (const float*)d_in[3];
    const float* temp  = (const float*)d_in[4];

    float* out  = (float*)d_out;
    float* rw   = out;
    float* disp = out + (size_t)N_ * E_;
    float* loss = out + (size_t)2 * N_ * E_;

    router_main<<<NBLK, 256>>>(x, W, gamma, beta, temp, rw, disp, loss);
}